// round 10
// baseline (speedup 1.0000x reference)
#include <cuda_runtime.h>
#include <math.h>

// SLAYFeatures: overlapped producer/expander in one kernel, roles interleaved
// in dispatch (blockIdx) order so both run concurrently on every SM.
//   producers (1024): NBP=8 rows -> g_poly + weighted g_prf, fence, set flag
//   expanders (8192): 1 row each; short spin on flag, stage 5KB smem,
//                     stream 16KB coalesced __stcs stores.
// Dispatch map: [LAG producers] + groups of 9 {producer q+LAG, 8 expanders of
// producer q} + tail expanders. Flags self-reset (8th consumer) => graph-replay safe.

#define NBP    8
#define THREADS 256
#define NPROD  1024
#define LAG    24
#define GROUPW 9

__device__ float g_poly[8192 * 256];     // 8 MB  [b][h*16+p]
__device__ float g_prf [8192 * 1024];    // 32 MB [b][r*512 + h*32 + m]
__device__ int   g_flag[NPROD];          // zero-init; self-reset each pass
__device__ int   g_done[NPROD];

__global__ __launch_bounds__(THREADS, 4) void slay_overlap(
    const float* __restrict__ x,        // [8192,1024]
    const float* __restrict__ omega,    // [2,16,64,32]
    const float* __restrict__ anchors,  // [16,64]
    float* __restrict__ out,            // [8192,16384]
    float s0, float s1, float c0, float c1, float e0, float e1)
{
    const int t = threadIdx.x;
    const int i = blockIdx.x;

    // ----- role decode: interleaved dispatch map -----
    int prod = -1, row = -1;
    if (i < LAG) {
        prod = i;
    } else if (i < LAG + GROUPW * (NPROD - LAG)) {
        int j = i - LAG;
        int q = j / GROUPW;
        int rem = j - q * GROUPW;
        if (rem == 0) prod = LAG + q;
        else          row  = q * 8 + (rem - 1);
    } else {
        row = (NPROD - LAG) * 8 + (i - (LAG + GROUPW * (NPROD - LAG)));
    }

    __shared__ __align__(16) float sh[NBP * 1024];   // 32 KB (union for both roles)

    if (prod >= 0) {
        // ================= PRODUCER (rows 8*prod .. 8*prod+7) =================
        float (*xs)[1024] = (float(*)[1024])sh;
        const int b0 = prod * NBP;

        // Phase 1: load + per-head normalize, two batches of 4 (reg peak <=64)
        {
            const float4* x4 = (const float4*)x;
#pragma unroll
            for (int half = 0; half < 2; half++) {
                float4 v[4];
                float  ss[4];
#pragma unroll
                for (int k = 0; k < 4; k++) {
                    v[k] = x4[(size_t)(b0 + half * 4 + k) * 256 + t];
                    ss[k] = v[k].x*v[k].x + v[k].y*v[k].y + v[k].z*v[k].z + v[k].w*v[k].w;
                }
#pragma unroll
                for (int k = 0; k < 4; k++) {
#pragma unroll
                    for (int off = 8; off; off >>= 1)
                        ss[k] += __shfl_xor_sync(0xffffffffu, ss[k], off);
                    float inv = 1.0f / (sqrtf(fmaxf(ss[k], 1e-12f)) + 1e-4f);
                    float4 w = v[k];
                    w.x *= inv; w.y *= inv; w.z *= inv; w.w *= inv;
                    ((float4*)xs[half * 4 + k])[t] = w;
                }
            }
        }
        __syncthreads();

        // Phase 2: poly -> g_poly. thread = (h, p)
        {
            const int h = t >> 4, p = t & 15;
            float acc[NBP];
#pragma unroll
            for (int k = 0; k < NBP; k++) acc[k] = 0.0f;
            const float4* an = (const float4*)(anchors + p * 64);
#pragma unroll 4
            for (int d4 = 0; d4 < 16; d4++) {
                float4 a = an[d4];
#pragma unroll
                for (int k = 0; k < NBP; k++) {
                    float4 xv = ((const float4*)xs[k])[h * 16 + d4];
                    acc[k] += xv.x*a.x + xv.y*a.y + xv.z*a.z + xv.w*a.w;
                }
            }
#pragma unroll
            for (int k = 0; k < NBP; k++)
                g_poly[(size_t)(b0 + k) * 256 + t] = acc[k] * acc[k] * 0.25f;
        }

        // Phase 3: prf -> g_prf. thread = (r, h, m4); omega amortized over 8 rows
        {
            const int r  = t >> 7;
            const int h  = (t >> 3) & 15;
            const int m4 = t & 7;

            float4 acc[NBP];
#pragma unroll
            for (int k = 0; k < NBP; k++) acc[k] = make_float4(0.f, 0.f, 0.f, 0.f);

            const float4* og = (const float4*)omega + (size_t)((r * 16 + h) * 64) * 8 + m4;
#pragma unroll 4
            for (int d4 = 0; d4 < 16; d4++) {
                float4 o0 = og[(4 * d4 + 0) * 8];
                float4 o1 = og[(4 * d4 + 1) * 8];
                float4 o2 = og[(4 * d4 + 2) * 8];
                float4 o3 = og[(4 * d4 + 3) * 8];
#pragma unroll
                for (int k = 0; k < NBP; k++) {
                    float4 xv = ((const float4*)xs[k])[h * 16 + d4];
                    acc[k].x += xv.x*o0.x; acc[k].y += xv.x*o0.y; acc[k].z += xv.x*o0.z; acc[k].w += xv.x*o0.w;
                    acc[k].x += xv.y*o1.x; acc[k].y += xv.y*o1.y; acc[k].z += xv.y*o1.z; acc[k].w += xv.y*o1.w;
                    acc[k].x += xv.z*o2.x; acc[k].y += xv.z*o2.y; acc[k].z += xv.z*o2.z; acc[k].w += xv.z*o2.w;
                    acc[k].x += xv.w*o3.x; acc[k].y += xv.w*o3.y; acc[k].z += xv.w*o3.z; acc[k].w += xv.w*o3.w;
                }
            }

            const float sr = r ? s1 : s0;
            const float cr = r ? c1 : c0;
            const float er = r ? e1 : e0;

#pragma unroll
            for (int k = 0; k < NBP; k++) {
                float4 a = acc[k];
                float4 pr;
                pr.x = er * __expf(fminf(fmaxf(a.x * cr - sr, -20.f), 20.f));
                pr.y = er * __expf(fminf(fmaxf(a.y * cr - sr, -20.f), 20.f));
                pr.z = er * __expf(fminf(fmaxf(a.z * cr - sr, -20.f), 20.f));
                pr.w = er * __expf(fminf(fmaxf(a.w * cr - sr, -20.f), 20.f));
                *(float4*)&g_prf[(size_t)(b0 + k) * 1024 + r * 512 + h * 32 + m4 * 4] = pr;
            }
        }

        // Release
        __threadfence();
        __syncthreads();
        if (t == 0) atomicExch(&g_flag[prod], 1);
    } else {
        // ================= EXPANDER (one row) =================
        float* pl = sh;          // 256 floats
        float* pf = sh + 256;    // 1024 floats

        const int b = row;
        const int f = b >> 3;    // flag index (8 rows per producer)

        if (t == 0) {
            while (atomicAdd(&g_flag[f], 0) == 0) __nanosleep(64);
            __threadfence();     // acquire
        }
        __syncthreads();

        pl[t] = g_poly[(size_t)b * 256 + t];
        ((float4*)pf)[t] = ((const float4*)(g_prf + (size_t)b * 1024))[t];
        __syncthreads();

        float4* ob = (float4*)(out + (size_t)b * 16384);
#pragma unroll
        for (int iidx = 0; iidx < 16; iidx++) {
            const int fi = iidx * 256 + t;    // float4 idx: r*2048 + h*128 + p*8 + m4
            const int m4 = fi & 7;
            const int p  = (fi >> 3) & 15;
            const int h  = (fi >> 7) & 15;
            const int r  = fi >> 11;
            const float s = pl[h * 16 + p];
            float4 v = ((const float4*)pf)[r * 128 + h * 8 + m4];
            v.x *= s; v.y *= s; v.z *= s; v.w *= s;
            __stcs(&ob[fi], v);
        }

        // Self-reset for next graph replay: 8th consumer zeroes flag + counter.
        __syncthreads();
        if (t == 0) {
            int prev = atomicAdd(&g_done[f], 1);
            if (prev == 7) {
                g_done[f] = 0;
                atomicExch(&g_flag[f], 0);
            }
        }
    }
}

extern "C" void kernel_launch(void* const* d_in, const int* in_sizes, int n_in,
                              void* d_out, int out_size) {
    const float* x       = (const float*)d_in[0];
    const float* omega   = (const float*)d_in[1];
    const float* anchors = (const float*)d_in[2];
    float* out = (float*)d_out;

    const double C   = 2.0 + 1e-6;
    const double rt2 = 1.4142135623730951;
    const double n0d = 2.0 - rt2, n1d = 2.0 + rt2;
    const double w0d = (2.0 + rt2) / 4.0, w1d = (2.0 - rt2) / 4.0;

    float s0 = (float)(n0d / C);
    float s1 = (float)(n1d / C);
    float c0 = sqrtf(2.0f * s0);
    float c1 = sqrtf(2.0f * s1);
    float invSqrtM = 1.0f / sqrtf(32.0f);
    float e0 = sqrtf((float)(w0d / C)) * invSqrtM;
    float e1 = sqrtf((float)(w1d / C)) * invSqrtM;

    // total blocks = LAG + 9*(NPROD-LAG) + 8*LAG = 24 + 9000 + 192 = 9216
    const int nblocks = LAG + GROUPW * (NPROD - LAG) + 8 * LAG;
    slay_overlap<<<nblocks, THREADS>>>(x, omega, anchors, out,
                                       s0, s1, c0, c1, e0, e1);
    (void)in_sizes; (void)n_in; (void)out_size;
}

// round 11
// speedup vs baseline: 2.1027x; 2.1027x over previous
#include <cuda_runtime.h>
#include <math.h>

// SLAYFeatures R11: persistent block pipelines TWO groups of 8 rows.
// Group A stores are interleaved into group B's phase-3 accumulate loop,
// overlapping A's DRAM store drain with B's FMA/LDG compute in-warp.
// out[b, r*8192 + h*512 + p*32 + m] = poly[b,h,p] * prf[b,r,h,m]

#define NB 8
#define THREADS 256

__global__ __launch_bounds__(THREADS, 2) void slay_kernel(
    const float* __restrict__ x,        // [8192,1024]
    const float* __restrict__ omega,    // [2,16,64,32]
    const float* __restrict__ anchors,  // [16,64]
    float* __restrict__ out,            // [8192,16384]
    float s0, float s1, float c0, float c1, float e0, float e1)
{
    __shared__ __align__(16) float xs[NB][1024];       // 32 KB, reused A then B
    __shared__ __align__(16) float poly_s[2][NB][256]; // 16 KB ping-pong

    const int t = threadIdx.x;

    // phase-3 thread mapping (fixed for both groups)
    const int r3  = t >> 7;
    const int h3  = (t >> 3) & 15;
    const int m43 = t & 7;
    const float sr = r3 ? s1 : s0;
    const float cr = r3 ? c1 : c0;
    const float er = r3 ? e1 : e0;
    const float4* og = (const float4*)omega + (size_t)((r3 * 16 + h3) * 64) * 8 + m43;

    float4 prA[NB];     // group-A prf values carried across barriers

#pragma unroll
    for (int grp = 0; grp < 2; grp++) {
        const int b0 = blockIdx.x * NB + grp * 4096;

        // ---------- Phase 1: load + per-head normalize ----------
        {
            const float4* x4 = (const float4*)x;
            float4 v[4]; float ss[4];
#pragma unroll
            for (int half = 0; half < 2; half++) {
#pragma unroll
                for (int k = 0; k < 4; k++) {
                    v[k] = x4[(size_t)(b0 + half * 4 + k) * 256 + t];
                    ss[k] = v[k].x*v[k].x + v[k].y*v[k].y + v[k].z*v[k].z + v[k].w*v[k].w;
                }
#pragma unroll
                for (int k = 0; k < 4; k++) {
#pragma unroll
                    for (int off = 8; off; off >>= 1)
                        ss[k] += __shfl_xor_sync(0xffffffffu, ss[k], off);
                    float inv = 1.0f / (sqrtf(fmaxf(ss[k], 1e-12f)) + 1e-4f);
                    float4 w = v[k];
                    w.x *= inv; w.y *= inv; w.z *= inv; w.w *= inv;
                    ((float4*)xs[half * 4 + k])[t] = w;
                }
            }
        }
        __syncthreads();

        // ---------- Phase 2: poly -> poly_s[grp] ----------
        {
            const int h = t >> 4, p = t & 15;
            float acc[NB];
#pragma unroll
            for (int k = 0; k < NB; k++) acc[k] = 0.0f;
            const float4* an = (const float4*)(anchors + p * 64);
#pragma unroll 4
            for (int d4 = 0; d4 < 16; d4++) {
                float4 a = an[d4];
#pragma unroll
                for (int k = 0; k < NB; k++) {
                    float4 xv = ((const float4*)xs[k])[h * 16 + d4];
                    acc[k] += xv.x*a.x + xv.y*a.y + xv.z*a.z + xv.w*a.w;
                }
            }
#pragma unroll
            for (int k = 0; k < NB; k++)
                poly_s[grp][k][t] = acc[k] * acc[k] * 0.25f;
        }
        __syncthreads();

        // ---------- Phase 3: accumulate; on grp==1 interleave group-A stores ----------
        {
            float4 acc[NB];
#pragma unroll
            for (int k = 0; k < NB; k++) acc[k] = make_float4(0.f, 0.f, 0.f, 0.f);

            const int b0A = blockIdx.x * NB;  // group-A rows (for interleaved stores)

#pragma unroll
            for (int d4 = 0; d4 < 16; d4++) {
                float4 o0 = og[(4 * d4 + 0) * 8];
                float4 o1 = og[(4 * d4 + 1) * 8];
                float4 o2 = og[(4 * d4 + 2) * 8];
                float4 o3 = og[(4 * d4 + 3) * 8];
#pragma unroll
                for (int k = 0; k < NB; k++) {
                    float4 xv = ((const float4*)xs[k])[h3 * 16 + d4];
                    acc[k].x += xv.x*o0.x; acc[k].y += xv.x*o0.y; acc[k].z += xv.x*o0.z; acc[k].w += xv.x*o0.w;
                    acc[k].x += xv.y*o1.x; acc[k].y += xv.y*o1.y; acc[k].z += xv.y*o1.z; acc[k].w += xv.y*o1.w;
                    acc[k].x += xv.z*o2.x; acc[k].y += xv.z*o2.y; acc[k].z += xv.z*o2.z; acc[k].w += xv.z*o2.w;
                    acc[k].x += xv.w*o3.x; acc[k].y += xv.w*o3.y; acc[k].z += xv.w*o3.z; acc[k].w += xv.w*o3.w;
                }
                if (grp == 1) {
                    // interleave 8 of group-A's 128 stores: row k = d4&7, p = (d4>>3)*8 ..+7
                    const int k  = d4 & 7;
                    const int p0 = (d4 >> 3) * 8;
                    float* ob = out + (size_t)(b0A + k) * 16384 + r3 * 8192 + h3 * 512 + m43 * 4;
                    const float* pl = &poly_s[0][k][h3 * 16];
                    float4 pa = prA[k];
#pragma unroll
                    for (int pp = 0; pp < 8; pp++) {
                        float pf = pl[p0 + pp];
                        float4 o;
                        o.x = pf * pa.x; o.y = pf * pa.y; o.z = pf * pa.z; o.w = pf * pa.w;
                        __stcs((float4*)(ob + (p0 + pp) * 32), o);
                    }
                }
            }

            // exp + quadrature weighting -> pr
#pragma unroll
            for (int k = 0; k < NB; k++) {
                float4 a = acc[k];
                float4 pr;
                pr.x = er * __expf(fminf(fmaxf(a.x * cr - sr, -20.f), 20.f));
                pr.y = er * __expf(fminf(fmaxf(a.y * cr - sr, -20.f), 20.f));
                pr.z = er * __expf(fminf(fmaxf(a.z * cr - sr, -20.f), 20.f));
                pr.w = er * __expf(fminf(fmaxf(a.w * cr - sr, -20.f), 20.f));
                prA[k] = pr;
            }
        }
        __syncthreads();   // xs free for next group; poly_s[grp] stable
    }

    // ---------- Tail: group-B stores ----------
    {
        const int b0B = blockIdx.x * NB + 4096;
#pragma unroll
        for (int k = 0; k < NB; k++) {
            float* ob = out + (size_t)(b0B + k) * 16384 + r3 * 8192 + h3 * 512 + m43 * 4;
            const float* pl = &poly_s[1][k][h3 * 16];
            float4 pa = prA[k];
#pragma unroll
            for (int p = 0; p < 16; p++) {
                float pf = pl[p];
                float4 o;
                o.x = pf * pa.x; o.y = pf * pa.y; o.z = pf * pa.z; o.w = pf * pa.w;
                __stcs((float4*)(ob + p * 32), o);
            }
        }
    }
}

extern "C" void kernel_launch(void* const* d_in, const int* in_sizes, int n_in,
                              void* d_out, int out_size) {
    const float* x       = (const float*)d_in[0];
    const float* omega   = (const float*)d_in[1];
    const float* anchors = (const float*)d_in[2];
    float* out = (float*)d_out;

    const double C   = 2.0 + 1e-6;
    const double rt2 = 1.4142135623730951;
    const double n0d = 2.0 - rt2, n1d = 2.0 + rt2;
    const double w0d = (2.0 + rt2) / 4.0, w1d = (2.0 - rt2) / 4.0;

    float s0 = (float)(n0d / C);
    float s1 = (float)(n1d / C);
    float c0 = sqrtf(2.0f * s0);
    float c1 = sqrtf(2.0f * s1);
    float invSqrtM = 1.0f / sqrtf(32.0f);
    float e0 = sqrtf((float)(w0d / C)) * invSqrtM;
    float e1 = sqrtf((float)(w1d / C)) * invSqrtM;

    slay_kernel<<<512, THREADS>>>(x, omega, anchors, out, s0, s1, c0, c1, e0, e1);
    (void)in_sizes; (void)n_in; (void)out_size;
}

// round 12
// speedup vs baseline: 2.4311x; 1.1562x over previous
#include <cuda_runtime.h>
#include <math.h>

// SLAYFeatures R12 = R5 + batch-split phase 3: stores of row-batch A are
// interleaved into row-batch B's accumulate loop (in-thread overlap of
// store drain with FMA/LDG compute; no cross-barrier register carries).
// out[b, r*8192 + h*512 + p*32 + m] = poly[b,h,p] * prf[b,r,h,m]

#define NB 8
#define THREADS 256

__global__ __launch_bounds__(THREADS, 3) void slay_kernel(
    const float* __restrict__ x,        // [8192,1024]
    const float* __restrict__ omega,    // [2,16,64,32]
    const float* __restrict__ anchors,  // [16,64]
    float* __restrict__ out,            // [8192,16384]
    float s0, float s1, float c0, float c1, float e0, float e1)
{
    __shared__ __align__(16) float xs[NB][1024];   // normalized x rows (32 KB)
    __shared__ __align__(16) float poly[NB][256];  // [b][h*16+p]        (8 KB)

    const int t  = threadIdx.x;
    const int b0 = blockIdx.x * NB;

    // ---------- Phase 1: load x, per-head normalize ----------
    {
        float4 v[NB];
        float  ss[NB];
        const float4* x4 = (const float4*)x;
#pragma unroll
        for (int k = 0; k < NB; k++) {
            v[k] = x4[(size_t)(b0 + k) * 256 + t];
            ss[k] = v[k].x*v[k].x + v[k].y*v[k].y + v[k].z*v[k].z + v[k].w*v[k].w;
        }
#pragma unroll
        for (int k = 0; k < NB; k++) {
#pragma unroll
            for (int off = 8; off; off >>= 1)
                ss[k] += __shfl_xor_sync(0xffffffffu, ss[k], off);
            float inv = 1.0f / (sqrtf(fmaxf(ss[k], 1e-12f)) + 1e-4f);
            float4 w = v[k];
            w.x *= inv; w.y *= inv; w.z *= inv; w.w *= inv;
            ((float4*)xs[k])[t] = w;
        }
    }
    __syncthreads();

    // ---------- Phase 2: poly features. thread = (h, p) ----------
    {
        const int h = t >> 4, p = t & 15;
        float acc[NB];
#pragma unroll
        for (int k = 0; k < NB; k++) acc[k] = 0.0f;
        const float4* an = (const float4*)(anchors + p * 64);
#pragma unroll 4
        for (int d4 = 0; d4 < 16; d4++) {
            float4 a = an[d4];
#pragma unroll
            for (int k = 0; k < NB; k++) {
                float4 xv = ((const float4*)xs[k])[h * 16 + d4];
                acc[k] += xv.x*a.x + xv.y*a.y + xv.z*a.z + xv.w*a.w;
            }
        }
#pragma unroll
        for (int k = 0; k < NB; k++)
            poly[k][t] = acc[k] * acc[k] * 0.25f;   // /sqrt(P=16)
    }
    __syncthreads();

    // ---------- Phase 3: batch-split PRF + interleaved stores ----------
    {
        const int r  = t >> 7;
        const int h  = (t >> 3) & 15;
        const int m4 = t & 7;
        const float sr = r ? s1 : s0;
        const float cr = r ? c1 : c0;
        const float er = r ? e1 : e0;
        const float4* og = (const float4*)omega + (size_t)((r * 16 + h) * 64) * 8 + m4;
        const size_t obase = r * 8192 + h * 512 + m4 * 4;

        // ---- Batch A: rows 0..3 accumulate ----
        float4 prA[4];
        {
            float4 acc[4];
#pragma unroll
            for (int k = 0; k < 4; k++) acc[k] = make_float4(0.f, 0.f, 0.f, 0.f);
#pragma unroll 4
            for (int d4 = 0; d4 < 16; d4++) {
                float4 o0 = og[(4 * d4 + 0) * 8];
                float4 o1 = og[(4 * d4 + 1) * 8];
                float4 o2 = og[(4 * d4 + 2) * 8];
                float4 o3 = og[(4 * d4 + 3) * 8];
#pragma unroll
                for (int k = 0; k < 4; k++) {
                    float4 xv = ((const float4*)xs[k])[h * 16 + d4];
                    acc[k].x += xv.x*o0.x; acc[k].y += xv.x*o0.y; acc[k].z += xv.x*o0.z; acc[k].w += xv.x*o0.w;
                    acc[k].x += xv.y*o1.x; acc[k].y += xv.y*o1.y; acc[k].z += xv.y*o1.z; acc[k].w += xv.y*o1.w;
                    acc[k].x += xv.z*o2.x; acc[k].y += xv.z*o2.y; acc[k].z += xv.z*o2.z; acc[k].w += xv.z*o2.w;
                    acc[k].x += xv.w*o3.x; acc[k].y += xv.w*o3.y; acc[k].z += xv.w*o3.z; acc[k].w += xv.w*o3.w;
                }
            }
#pragma unroll
            for (int k = 0; k < 4; k++) {
                float4 a = acc[k];
                prA[k].x = er * __expf(fminf(fmaxf(a.x * cr - sr, -20.f), 20.f));
                prA[k].y = er * __expf(fminf(fmaxf(a.y * cr - sr, -20.f), 20.f));
                prA[k].z = er * __expf(fminf(fmaxf(a.z * cr - sr, -20.f), 20.f));
                prA[k].w = er * __expf(fminf(fmaxf(a.w * cr - sr, -20.f), 20.f));
            }
        }

        // ---- Batch B: rows 4..7 accumulate, A's 64 stores interleaved ----
        {
            float4 acc[4];
#pragma unroll
            for (int k = 0; k < 4; k++) acc[k] = make_float4(0.f, 0.f, 0.f, 0.f);
#pragma unroll
            for (int d4 = 0; d4 < 16; d4++) {
                float4 o0 = og[(4 * d4 + 0) * 8];
                float4 o1 = og[(4 * d4 + 1) * 8];
                float4 o2 = og[(4 * d4 + 2) * 8];
                float4 o3 = og[(4 * d4 + 3) * 8];
#pragma unroll
                for (int k = 0; k < 4; k++) {
                    float4 xv = ((const float4*)xs[4 + k])[h * 16 + d4];
                    acc[k].x += xv.x*o0.x; acc[k].y += xv.x*o0.y; acc[k].z += xv.x*o0.z; acc[k].w += xv.x*o0.w;
                    acc[k].x += xv.y*o1.x; acc[k].y += xv.y*o1.y; acc[k].z += xv.y*o1.z; acc[k].w += xv.y*o1.w;
                    acc[k].x += xv.z*o2.x; acc[k].y += xv.z*o2.y; acc[k].z += xv.z*o2.z; acc[k].w += xv.z*o2.w;
                    acc[k].x += xv.w*o3.x; acc[k].y += xv.w*o3.y; acc[k].z += xv.w*o3.z; acc[k].w += xv.w*o3.w;
                }
                // interleave 4 of batch A's 64 stores: row = d4&3, p-group = d4>>2
                {
                    const int k  = d4 & 3;
                    const int p0 = (d4 >> 2) * 4;
                    float* ob = out + (size_t)(b0 + k) * 16384 + obase;
                    const float* pl = &poly[k][h * 16];
                    float4 pa = prA[k];
#pragma unroll
                    for (int pp = 0; pp < 4; pp++) {
                        float pf = pl[p0 + pp];
                        float4 o;
                        o.x = pf * pa.x; o.y = pf * pa.y; o.z = pf * pa.z; o.w = pf * pa.w;
                        __stcs((float4*)(ob + (p0 + pp) * 32), o);
                    }
                }
            }
            // exp + store batch B
#pragma unroll
            for (int k = 0; k < 4; k++) {
                float4 a = acc[k];
                float4 pr;
                pr.x = er * __expf(fminf(fmaxf(a.x * cr - sr, -20.f), 20.f));
                pr.y = er * __expf(fminf(fmaxf(a.y * cr - sr, -20.f), 20.f));
                pr.z = er * __expf(fminf(fmaxf(a.z * cr - sr, -20.f), 20.f));
                pr.w = er * __expf(fminf(fmaxf(a.w * cr - sr, -20.f), 20.f));

                float* ob = out + (size_t)(b0 + 4 + k) * 16384 + obase;
                const float* pl = &poly[4 + k][h * 16];
#pragma unroll
                for (int p = 0; p < 16; p++) {
                    float pf = pl[p];
                    float4 o;
                    o.x = pf * pr.x; o.y = pf * pr.y; o.z = pf * pr.z; o.w = pf * pr.w;
                    __stcs((float4*)(ob + p * 32), o);
                }
            }
        }
    }
}

extern "C" void kernel_launch(void* const* d_in, const int* in_sizes, int n_in,
                              void* d_out, int out_size) {
    const float* x       = (const float*)d_in[0];
    const float* omega   = (const float*)d_in[1];
    const float* anchors = (const float*)d_in[2];
    float* out = (float*)d_out;

    const double C   = 2.0 + 1e-6;
    const double rt2 = 1.4142135623730951;
    const double n0d = 2.0 - rt2, n1d = 2.0 + rt2;
    const double w0d = (2.0 + rt2) / 4.0, w1d = (2.0 - rt2) / 4.0;

    float s0 = (float)(n0d / C);
    float s1 = (float)(n1d / C);
    float c0 = sqrtf(2.0f * s0);
    float c1 = sqrtf(2.0f * s1);
    float invSqrtM = 1.0f / sqrtf(32.0f);
    float e0 = sqrtf((float)(w0d / C)) * invSqrtM;
    float e1 = sqrtf((float)(w1d / C)) * invSqrtM;

    slay_kernel<<<8192 / NB, THREADS>>>(x, omega, anchors, out,
                                        s0, s1, c0, c1, e0, e1);
    (void)in_sizes; (void)n_in; (void)out_size;
}